// round 1
// baseline (speedup 1.0000x reference)
#include <cuda_runtime.h>
#include <cstdint>

// Problem shape (fixed by the dataset)
static constexpr int B = 64;
static constexpr int N = 20000;
static constexpr int E = 1280000;

// Scratch: xT [N][64] and accumulator [N][64], both as float4[N][16].
// __device__ globals (no allocation allowed in kernel_launch).
__device__ float4 g_xT[N * 16];
__device__ float4 g_acc[N * 16];

// ---------------------------------------------------------------------------
// Kernel 1: zero the accumulator
// ---------------------------------------------------------------------------
__global__ void zero_kernel() {
    int i = blockIdx.x * blockDim.x + threadIdx.x;
    if (i < N * 16) g_acc[i] = make_float4(0.f, 0.f, 0.f, 0.f);
}

// ---------------------------------------------------------------------------
// Kernel 2: transpose x [B, N] -> xT [N, B] (classic 32x32 smem tiles)
// N % 32 == 0, B % 32 == 0, so no bounds checks needed.
// ---------------------------------------------------------------------------
__global__ void transpose_kernel(const float* __restrict__ x) {
    __shared__ float tile[32][33];
    float* xT = reinterpret_cast<float*>(g_xT);

    int n0 = blockIdx.x * 32;
    int b0 = blockIdx.y * 32;
    int tx = threadIdx.x;   // 0..31
    int ty = threadIdx.y;   // 0..7

#pragma unroll
    for (int i = 0; i < 32; i += 8) {
        tile[ty + i][tx] = x[(b0 + ty + i) * N + (n0 + tx)];
    }
    __syncthreads();
#pragma unroll
    for (int i = 0; i < 32; i += 8) {
        // xT[n, b] = x[b, n]
        xT[(n0 + ty + i) * B + (b0 + tx)] = tile[tx][ty + i];
    }
}

// ---------------------------------------------------------------------------
// Kernel 3: edge scatter. 16 lanes per edge, one float4 per lane.
//   acc[dst[e], :] += (adj[e]*w[e]) * xT[src[e], :]
// Uses red.global.add.v4.f32 (no-return vector reduction, sm_90+).
// ---------------------------------------------------------------------------
__global__ __launch_bounds__(256) void scatter_kernel(
    const float* __restrict__ adj, const float* __restrict__ w,
    const int* __restrict__ src, const int* __restrict__ dst)
{
    int t = blockIdx.x * 256 + threadIdx.x;
    int e = t >> 4;          // edge index
    if (e >= E) return;
    int sub = t & 15;        // which float4 of the 64-wide row

    int   s = __ldg(src + e);
    int   d = __ldg(dst + e);
    float c = __ldg(adj + e) * __ldg(w + e);

    float4 xv = g_xT[s * 16 + sub];
    float4 v  = make_float4(c * xv.x, c * xv.y, c * xv.z, c * xv.w);

    unsigned long long p =
        (unsigned long long)__cvta_generic_to_global(&g_acc[d * 16 + sub]);
    asm volatile("red.global.add.v4.f32 [%0], {%1, %2, %3, %4};"
                 :: "l"(p), "f"(v.x), "f"(v.y), "f"(v.z), "f"(v.w)
                 : "memory");
}

// ---------------------------------------------------------------------------
// Kernel 4: epilogue. out[b, n] = relu(acc[n, b] * (x[0, n]*self_w[n]) + bias[n])
// Output writes are coalesced over n; acc reads are L2-resident.
// ---------------------------------------------------------------------------
__global__ __launch_bounds__(256) void epilogue_kernel(
    const float* __restrict__ x, const float* __restrict__ self_w,
    const float* __restrict__ bias, float* __restrict__ out)
{
    int idx = blockIdx.x * 256 + threadIdx.x;
    if (idx >= B * N) return;
    int b = idx / N;
    int n = idx - b * N;

    const float* acc = reinterpret_cast<const float*>(g_acc);
    float sl = __ldg(x + n) * __ldg(self_w + n);   // x row 0 -> self loop
    float v  = fmaf(acc[n * B + b], sl, __ldg(bias + n));
    out[idx] = fmaxf(v, 0.f);
}

// ---------------------------------------------------------------------------
// Launch
// ---------------------------------------------------------------------------
extern "C" void kernel_launch(void* const* d_in, const int* in_sizes, int n_in,
                              void* d_out, int out_size)
{
    const float* x      = (const float*)d_in[0];
    const float* adj    = (const float*)d_in[1];
    const float* w      = (const float*)d_in[2];
    const float* self_w = (const float*)d_in[3];
    const float* bias   = (const float*)d_in[4];
    const int*   src    = (const int*)d_in[5];
    const int*   dst    = (const int*)d_in[6];
    float*       out    = (float*)d_out;

    zero_kernel<<<(N * 16 + 255) / 256, 256>>>();
    transpose_kernel<<<dim3(N / 32, B / 32), dim3(32, 8)>>>(x);
    scatter_kernel<<<(E * 16) / 256, 256>>>(adj, w, src, dst);
    epilogue_kernel<<<(B * N + 255) / 256, 256>>>(x, self_w, bias, out);
}